// round 12
// baseline (speedup 1.0000x reference)
#include <cuda_runtime.h>
#include <cuda_bf16.h>
#include <math.h>
#include <cstdint>

static constexpr int BATCH = 8;
static constexpr int NQ = 2048;
static constexpr int NK = 2048;
static constexpr int DH = 512;

// ---------------- device scratch (no allocs allowed) ----------------
__device__ float g_S[(size_t)BATCH * NQ * NK];                      // 128 MiB
__device__ __nv_bfloat16 g_Qhi[(size_t)BATCH * NQ * DH];
__device__ __nv_bfloat16 g_Qlo[(size_t)BATCH * NQ * DH];
__device__ __nv_bfloat16 g_Khi[(size_t)BATCH * NK * DH];
__device__ __nv_bfloat16 g_Klo[(size_t)BATCH * NK * DH];
__device__ __nv_bfloat16 g_Kthi[(size_t)BATCH * DH * NK];           // K^T [B, DH, NK]
__device__ __nv_bfloat16 g_Ktlo[(size_t)BATCH * DH * NK];
__device__ __nv_bfloat16 g_Phi[(size_t)BATCH * NQ * NK];            // 64 MiB
__device__ __nv_bfloat16 g_Plo[(size_t)BATCH * NQ * NK];

// ---------------- helpers (sm_80-era PTX only: safe on compute_103) --------
__device__ __forceinline__ uint32_t smem_u32(const void* p) {
    uint32_t a;
    asm("{ .reg .u64 t; cvta.to.shared.u64 t, %1; cvt.u32.u64 %0, t; }" : "=r"(a) : "l"(p));
    return a;
}
__device__ __forceinline__ void cpa16(uint32_t dst, const void* src) {
    asm volatile("cp.async.cg.shared.global [%0], [%1], 16;" :: "r"(dst), "l"(src));
}
__device__ __forceinline__ void cpa_commit() { asm volatile("cp.async.commit_group;" ::: "memory"); }
__device__ __forceinline__ void cpa_wait1()  { asm volatile("cp.async.wait_group 1;" ::: "memory"); }

#define LDSM4(r, addr) \
    asm volatile("ldmatrix.sync.aligned.m8n8.x4.shared.b16 {%0,%1,%2,%3}, [%4];" \
                 : "=r"((r)[0]), "=r"((r)[1]), "=r"((r)[2]), "=r"((r)[3]) : "r"(addr))

#define MMA16816(d, a, b0v, b1v) \
    asm volatile("mma.sync.aligned.m16n8k16.row.col.f32.bf16.bf16.f32 " \
                 "{%0,%1,%2,%3}, {%4,%5,%6,%7}, {%8,%9}, {%0,%1,%2,%3};" \
                 : "+f"((d)[0]), "+f"((d)[1]), "+f"((d)[2]), "+f"((d)[3]) \
                 : "r"((a)[0]), "r"((a)[1]), "r"((a)[2]), "r"((a)[3]), \
                   "r"(b0v), "r"(b1v))

// ---------------------------------------------------------------------------
// Split-bf16 GEMM via mma.sync: C = (Ahi+Alo)*(Bhi+Blo)^T, dropping lo*lo.
// 128x128 tile/CTA, 128 threads, 2x2 warp grid -> 64x64 warp tiles.
// One smem stage holds Ahi|Alo|Bhi|Blo (4 x 10240B); 2-stage ring, BK=32.
// SMEM rows padded to 80B -> conflict-free ldmatrix.
// ---------------------------------------------------------------------------
static constexpr int ROWB = 80;                   // bytes per smem row
static constexpr int BTILE = 128 * ROWB;          // 10240 B per operand tile
static constexpr int STAGE = 4 * BTILE;           // Ahi+Alo+Bhi+Blo (40960 B)
static constexpr int STAGES = 2;
static constexpr int GEMM_SMEM = STAGES * STAGE;  // 81920 B

__global__ __launch_bounds__(128, 2)
void gemm_mma_kernel(const __nv_bfloat16* __restrict__ Ahi, const __nv_bfloat16* __restrict__ Alo,
                     const __nv_bfloat16* __restrict__ Bhi, const __nv_bfloat16* __restrict__ Blo,
                     float* __restrict__ C, int M, int N, int K)
{
    extern __shared__ char smem[];
    const uint32_t sb = smem_u32(smem);
    const int tid = threadIdx.x;
    const int warp = tid >> 5, lane = tid & 31;
    const int wm = warp >> 1, wn = warp & 1;       // 2 x 2 warp grid, 64x64 tiles
    const int bz = blockIdx.z;
    const int m0 = blockIdx.y * 128, n0 = blockIdx.x * 128;

    const size_t offA = (size_t)bz * M * K + (size_t)m0 * K;
    const size_t offB = (size_t)bz * N * K + (size_t)n0 * K;
    const __nv_bfloat16* gAhi = Ahi + offA;
    const __nv_bfloat16* gAlo = Alo + offA;
    const __nv_bfloat16* gBhi = Bhi + offB;
    const __nv_bfloat16* gBlo = Blo + offB;

    const int KC = K / 32;         // K-chunks

    const int lr = tid >> 2;       // 0..31  (load row base)
    const int ls = tid & 3;        // 0..3   (16B chunk within 64B row)

    // Load one K-chunk: 4 tiles x 128 rows; 16 cp.async per thread.
    auto load_chunk = [&](int c, uint32_t buf) {
        const size_t kb = (size_t)c * 64;          // byte offset along K
        const char* tp[4] = {(const char*)gAhi + kb, (const char*)gAlo + kb,
                             (const char*)gBhi + kb, (const char*)gBlo + kb};
        #pragma unroll
        for (int t = 0; t < 4; t++) {
            const uint32_t tb = buf + (uint32_t)t * BTILE;
            #pragma unroll
            for (int rr = 0; rr < 4; rr++) {
                const int row = lr + rr * 32;
                cpa16(tb + row * ROWB + ls * 16, tp[t] + (size_t)row * K * 2 + ls * 16);
            }
        }
    };

    load_chunk(0, sb);          cpa_commit();
    load_chunk(1, sb + STAGE);  cpa_commit();

    float acc[4][8][4];
    #pragma unroll
    for (int i = 0; i < 4; i++)
        #pragma unroll
        for (int j = 0; j < 8; j++)
            #pragma unroll
            for (int r = 0; r < 4; r++) acc[i][j][r] = 0.0f;

    // ldmatrix per-lane base offsets within a tile
    const uint32_t aoff = (uint32_t)((wm * 64 + (lane & 15)) * ROWB + (lane >> 4) * 16);
    const uint32_t boff = (uint32_t)((wn * 64 + (lane & 15)) * ROWB + (lane >> 4) * 16);

    for (int c = 0; c < KC; c++) {
        const uint32_t bp = sb + (uint32_t)(c & 1) * STAGE;
        cpa_wait1();
        __syncthreads();

        #pragma unroll
        for (int ks = 0; ks < 2; ks++) {
            const uint32_t ko = (uint32_t)(ks * 32);
            uint32_t ah[4][4], bh[4][4];
            #pragma unroll
            for (int mi = 0; mi < 4; mi++)
                LDSM4(ah[mi], bp + aoff + mi * 16 * ROWB + ko);
            #pragma unroll
            for (int nb = 0; nb < 4; nb++)
                LDSM4(bh[nb], bp + 2 * BTILE + boff + nb * 16 * ROWB + ko);

            // hi * hi
            #pragma unroll
            for (int mi = 0; mi < 4; mi++)
                #pragma unroll
                for (int nb = 0; nb < 4; nb++) {
                    MMA16816(acc[mi][nb * 2 + 0], ah[mi], bh[nb][0], bh[nb][2]);
                    MMA16816(acc[mi][nb * 2 + 1], ah[mi], bh[nb][1], bh[nb][3]);
                }
            // lo * hi  (reuse bh; al scoped)
            {
                uint32_t al[4][4];
                #pragma unroll
                for (int mi = 0; mi < 4; mi++)
                    LDSM4(al[mi], bp + BTILE + aoff + mi * 16 * ROWB + ko);
                #pragma unroll
                for (int mi = 0; mi < 4; mi++)
                    #pragma unroll
                    for (int nb = 0; nb < 4; nb++) {
                        MMA16816(acc[mi][nb * 2 + 0], al[mi], bh[nb][0], bh[nb][2]);
                        MMA16816(acc[mi][nb * 2 + 1], al[mi], bh[nb][1], bh[nb][3]);
                    }
            }
            // hi * lo  (reuse ah; bl scoped)
            {
                uint32_t bl[4][4];
                #pragma unroll
                for (int nb = 0; nb < 4; nb++)
                    LDSM4(bl[nb], bp + 3 * BTILE + boff + nb * 16 * ROWB + ko);
                #pragma unroll
                for (int mi = 0; mi < 4; mi++)
                    #pragma unroll
                    for (int nb = 0; nb < 4; nb++) {
                        MMA16816(acc[mi][nb * 2 + 0], ah[mi], bl[nb][0], bl[nb][2]);
                        MMA16816(acc[mi][nb * 2 + 1], ah[mi], bl[nb][1], bl[nb][3]);
                    }
            }
        }

        __syncthreads();           // all warps done reading this slot
        if (c + 2 < KC) load_chunk(c + 2, bp);
        cpa_commit();
    }

    // Epilogue: fragment layout m16n8: c0,c1 @ (row, 2*(lane%4)); c2,c3 @ row+8
    float* pC = C + (size_t)bz * M * N + (size_t)(m0 + wm * 64) * N + n0 + wn * 64;
    const int er = lane >> 2, ec = (lane & 3) * 2;
    #pragma unroll
    for (int mi = 0; mi < 4; mi++) {
        #pragma unroll
        for (int ni = 0; ni < 8; ni++) {
            float* d0 = pC + (size_t)(mi * 16 + er) * N + ni * 8 + ec;
            float* d1 = d0 + (size_t)8 * N;
            *(float2*)d0 = make_float2(acc[mi][ni][0], acc[mi][ni][1]);
            *(float2*)d1 = make_float2(acc[mi][ni][2], acc[mi][ni][3]);
        }
    }
}

// ---------------------------------------------------------------------------
// fp32 -> (bf16 hi, bf16 lo) elementwise split; 4 elems/thread
// ---------------------------------------------------------------------------
__global__ __launch_bounds__(256)
void split_kernel(const float* __restrict__ x, __nv_bfloat16* __restrict__ hi,
                  __nv_bfloat16* __restrict__ lo) {
    const size_t i = ((size_t)blockIdx.x * 256 + threadIdx.x) * 4;
    const float4 v = *(const float4*)(x + i);
    __nv_bfloat162 h0, h1, l0, l1;
    h0.x = __float2bfloat16(v.x); h0.y = __float2bfloat16(v.y);
    h1.x = __float2bfloat16(v.z); h1.y = __float2bfloat16(v.w);
    l0.x = __float2bfloat16(v.x - __bfloat162float(h0.x));
    l0.y = __float2bfloat16(v.y - __bfloat162float(h0.y));
    l1.x = __float2bfloat16(v.z - __bfloat162float(h1.x));
    l1.y = __float2bfloat16(v.w - __bfloat162float(h1.y));
    ((__nv_bfloat162*)(hi + i))[0] = h0; ((__nv_bfloat162*)(hi + i))[1] = h1;
    ((__nv_bfloat162*)(lo + i))[0] = l0; ((__nv_bfloat162*)(lo + i))[1] = l1;
}

// ---------------------------------------------------------------------------
// K [B, NK, DH] fp32 -> transposed splits [B, DH, NK] bf16 hi/lo
// ---------------------------------------------------------------------------
__global__ __launch_bounds__(256)
void transpose_split_kernel(const float* __restrict__ Kin,
                            __nv_bfloat16* __restrict__ Thi,
                            __nv_bfloat16* __restrict__ Tlo) {
    __shared__ float tile[32][33];
    const int b = blockIdx.z;
    const int n0 = blockIdx.x * 32, d0 = blockIdx.y * 32;
    const int tx = threadIdx.x, ty = threadIdx.y;   // (32, 8)
    const float* src = Kin + (size_t)b * NK * DH;
    #pragma unroll
    for (int j = 0; j < 32; j += 8)
        tile[ty + j][tx] = src[(size_t)(n0 + ty + j) * DH + d0 + tx];
    __syncthreads();
    __nv_bfloat16* th = Thi + (size_t)b * DH * NK;
    __nv_bfloat16* tl = Tlo + (size_t)b * DH * NK;
    #pragma unroll
    for (int j = 0; j < 32; j += 8) {
        const float v = tile[tx][ty + j];
        const __nv_bfloat16 h = __float2bfloat16(v);
        th[(size_t)(d0 + ty + j) * NK + n0 + tx] = h;
        tl[(size_t)(d0 + ty + j) * NK + n0 + tx] = __float2bfloat16(v - __bfloat162float(h));
    }
}

// ---------------------------------------------------------------------------
// Row softmax over NK, emitting split-bf16 probabilities.
// ---------------------------------------------------------------------------
__device__ __forceinline__ void store_split2(__nv_bfloat162* ph, __nv_bfloat162* pl,
                                             float a, float b) {
    __nv_bfloat162 h, l;
    h.x = __float2bfloat16(a); h.y = __float2bfloat16(b);
    l.x = __float2bfloat16(a - __bfloat162float(h.x));
    l.y = __float2bfloat16(b - __bfloat162float(h.y));
    *ph = h; *pl = l;
}

__global__ __launch_bounds__(256)
void softmax_split_kernel(const float* __restrict__ S,
                          __nv_bfloat16* __restrict__ Phi,
                          __nv_bfloat16* __restrict__ Plo) {
    const float* row = S + (size_t)blockIdx.x * NK;
    __nv_bfloat162* ph = (__nv_bfloat162*)(Phi + (size_t)blockIdx.x * NK);
    __nv_bfloat162* pl = (__nv_bfloat162*)(Plo + (size_t)blockIdx.x * NK);
    const int tid = threadIdx.x;

    float4 v0 = *(const float4*)(row + (size_t)tid * 4);
    float4 v1 = *(const float4*)(row + (size_t)(tid + 256) * 4);

    float mx = fmaxf(fmaxf(fmaxf(v0.x, v0.y), fmaxf(v0.z, v0.w)),
                     fmaxf(fmaxf(v1.x, v1.y), fmaxf(v1.z, v1.w)));

    __shared__ float shm[8];
    __shared__ float shs[8];

    #pragma unroll
    for (int o = 16; o; o >>= 1) mx = fmaxf(mx, __shfl_xor_sync(0xffffffffu, mx, o));
    if ((tid & 31) == 0) shm[tid >> 5] = mx;
    __syncthreads();
    mx = shm[0];
    #pragma unroll
    for (int i = 1; i < 8; i++) mx = fmaxf(mx, shm[i]);

    v0.x = __expf(v0.x - mx); v0.y = __expf(v0.y - mx);
    v0.z = __expf(v0.z - mx); v0.w = __expf(v0.w - mx);
    v1.x = __expf(v1.x - mx); v1.y = __expf(v1.y - mx);
    v1.z = __expf(v1.z - mx); v1.w = __expf(v1.w - mx);

    float s = v0.x + v0.y + v0.z + v0.w + v1.x + v1.y + v1.z + v1.w;
    #pragma unroll
    for (int o = 16; o; o >>= 1) s += __shfl_xor_sync(0xffffffffu, s, o);
    if ((tid & 31) == 0) shs[tid >> 5] = s;
    __syncthreads();
    s = 0.0f;
    #pragma unroll
    for (int i = 0; i < 8; i++) s += shs[i];

    const float inv = 1.0f / s;
    v0.x *= inv; v0.y *= inv; v0.z *= inv; v0.w *= inv;
    v1.x *= inv; v1.y *= inv; v1.z *= inv; v1.w *= inv;

    store_split2(ph + (size_t)tid * 2 + 0, pl + (size_t)tid * 2 + 0, v0.x, v0.y);
    store_split2(ph + (size_t)tid * 2 + 1, pl + (size_t)tid * 2 + 1, v0.z, v0.w);
    store_split2(ph + (size_t)(tid + 256) * 2 + 0, pl + (size_t)(tid + 256) * 2 + 0, v1.x, v1.y);
    store_split2(ph + (size_t)(tid + 256) * 2 + 1, pl + (size_t)(tid + 256) * 2 + 1, v1.z, v1.w);
}

// ---------------------------------------------------------------------------
extern "C" void kernel_launch(void* const* d_in, const int* in_sizes, int n_in,
                              void* d_out, int out_size) {
    const float* Q  = (const float*)d_in[0];   // [B, NQ, DH]
    const float* Kp = (const float*)d_in[1];   // [B, NK, DH]
    float* O = (float*)d_out;                  // [B, NQ, DH]

    float* S; __nv_bfloat16 *qhi, *qlo, *khi, *klo, *kthi, *ktlo, *phi, *plo;
    cudaGetSymbolAddress((void**)&S,    g_S);
    cudaGetSymbolAddress((void**)&qhi,  g_Qhi);
    cudaGetSymbolAddress((void**)&qlo,  g_Qlo);
    cudaGetSymbolAddress((void**)&khi,  g_Khi);
    cudaGetSymbolAddress((void**)&klo,  g_Klo);
    cudaGetSymbolAddress((void**)&kthi, g_Kthi);
    cudaGetSymbolAddress((void**)&ktlo, g_Ktlo);
    cudaGetSymbolAddress((void**)&phi,  g_Phi);
    cudaGetSymbolAddress((void**)&plo,  g_Plo);

    cudaFuncSetAttribute(gemm_mma_kernel, cudaFuncAttributeMaxDynamicSharedMemorySize, GEMM_SMEM);

    const int splitBlocks = (BATCH * NQ * DH) / (256 * 4);   // 8192

    split_kernel<<<splitBlocks, 256>>>(Q, qhi, qlo);
    split_kernel<<<splitBlocks, 256>>>(Kp, khi, klo);
    transpose_split_kernel<<<dim3(NK / 32, DH / 32, BATCH), dim3(32, 8)>>>(Kp, kthi, ktlo);

    // S = Q K^T   (M=2048, N=2048, K=512)
    gemm_mma_kernel<<<dim3(NK / 128, NQ / 128, BATCH), 128, GEMM_SMEM>>>(
        qhi, qlo, khi, klo, S, NQ, NK, DH);

    // P = softmax(S), split to bf16 hi/lo
    softmax_split_kernel<<<BATCH * NQ, 256>>>(S, phi, plo);

    // O = P K     (M=2048, N=512, K=2048), B = K^T (transposed splits, K-major)
    gemm_mma_kernel<<<dim3(DH / 128, NQ / 128, BATCH), 128, GEMM_SMEM>>>(
        phi, plo, kthi, ktlo, O, NQ, DH, NK);
}

// round 14
// speedup vs baseline: 1.1399x; 1.1399x over previous
#include <cuda_runtime.h>
#include <cuda_bf16.h>
#include <math.h>
#include <cstdint>

static constexpr int BATCH = 8;
static constexpr int NQ = 2048;
static constexpr int NK = 2048;
static constexpr int DH = 512;

// ---------------- device scratch (no allocs allowed) ----------------
__device__ float g_S[(size_t)BATCH * NQ * NK];                      // 128 MiB
__device__ __nv_bfloat16 g_Qhi[(size_t)BATCH * NQ * DH];
__device__ __nv_bfloat16 g_Qlo[(size_t)BATCH * NQ * DH];
__device__ __nv_bfloat16 g_Khi[(size_t)BATCH * NK * DH];
__device__ __nv_bfloat16 g_Klo[(size_t)BATCH * NK * DH];
__device__ __nv_bfloat16 g_Kthi[(size_t)BATCH * DH * NK];           // K^T [B, DH, NK]
__device__ __nv_bfloat16 g_Ktlo[(size_t)BATCH * DH * NK];
__device__ __nv_bfloat16 g_Phi[(size_t)BATCH * NQ * NK];            // 64 MiB
__device__ __nv_bfloat16 g_Plo[(size_t)BATCH * NQ * NK];

// ---------------- helpers (sm_80-era PTX only: safe on compute_103) --------
__device__ __forceinline__ uint32_t smem_u32(const void* p) {
    uint32_t a;
    asm("{ .reg .u64 t; cvta.to.shared.u64 t, %1; cvt.u32.u64 %0, t; }" : "=r"(a) : "l"(p));
    return a;
}
__device__ __forceinline__ void cpa16(uint32_t dst, const void* src) {
    asm volatile("cp.async.cg.shared.global [%0], [%1], 16;" :: "r"(dst), "l"(src));
}
__device__ __forceinline__ void cpa_commit() { asm volatile("cp.async.commit_group;" ::: "memory"); }
__device__ __forceinline__ void cpa_wait1()  { asm volatile("cp.async.wait_group 1;" ::: "memory"); }

#define LDSM4(r, addr) \
    asm volatile("ldmatrix.sync.aligned.m8n8.x4.shared.b16 {%0,%1,%2,%3}, [%4];" \
                 : "=r"((r)[0]), "=r"((r)[1]), "=r"((r)[2]), "=r"((r)[3]) : "r"(addr))

#define MMA16816(d, a, b0v, b1v) \
    asm volatile("mma.sync.aligned.m16n8k16.row.col.f32.bf16.bf16.f32 " \
                 "{%0,%1,%2,%3}, {%4,%5,%6,%7}, {%8,%9}, {%0,%1,%2,%3};" \
                 : "+f"((d)[0]), "+f"((d)[1]), "+f"((d)[2]), "+f"((d)[3]) \
                 : "r"((a)[0]), "r"((a)[1]), "r"((a)[2]), "r"((a)[3]), \
                   "r"(b0v), "r"(b1v))

// ---------------------------------------------------------------------------
// Split-bf16 GEMM via mma.sync: C = (Ahi+Alo)*(Bhi+Blo)^T, dropping lo*lo.
// 128x128 tile/CTA, 256 threads, 2x4 warp grid -> 64x32 warp tiles, BK=32.
// SMEM: 64B rows with XOR swizzle (phys_col16 = col16 ^ ((row>>1)&3)) ->
// conflict-free LDSM with NO padding. 3-stage ring, ONE __syncthreads per
// chunk (wait -> barrier -> refill (c-1)%3 slot -> compute), CUTLASS-style.
// ---------------------------------------------------------------------------
static constexpr int ROWB = 64;                   // bytes per smem row (no pad)
static constexpr int BTILE = 128 * ROWB;          // 8192 B per operand tile
static constexpr int STAGE = 4 * BTILE;           // Ahi|Alo|Bhi|Blo (32768 B)
static constexpr int STAGES = 3;
static constexpr int GEMM_SMEM = STAGES * STAGE;  // 98304 B

__global__ __launch_bounds__(256, 2)
void gemm_mma_kernel(const __nv_bfloat16* __restrict__ Ahi, const __nv_bfloat16* __restrict__ Alo,
                     const __nv_bfloat16* __restrict__ Bhi, const __nv_bfloat16* __restrict__ Blo,
                     float* __restrict__ C, int M, int N, int K)
{
    extern __shared__ char smem[];
    const uint32_t sb = smem_u32(smem);
    const int tid = threadIdx.x;
    const int warp = tid >> 5, lane = tid & 31;
    const int wm = warp >> 2, wn = warp & 3;       // 2 x 4 warp grid
    const int bz = blockIdx.z;
    const int m0 = blockIdx.y * 128, n0 = blockIdx.x * 128;

    const size_t offA = (size_t)bz * M * K + (size_t)m0 * K;
    const size_t offB = (size_t)bz * N * K + (size_t)n0 * K;
    const __nv_bfloat16* gAhi = Ahi + offA;
    const __nv_bfloat16* gAlo = Alo + offA;
    const __nv_bfloat16* gBhi = Bhi + offB;
    const __nv_bfloat16* gBlo = Blo + offB;

    const int KC = K / 32;         // K-chunks

    const int lr = tid >> 2;       // 0..63  (load row)
    const int ls = tid & 3;        // 0..3   (logical 16B chunk within 64B row)
    // swizzled physical column for this thread's rows (invariant for lr and lr+64)
    const int pc = ls ^ ((lr >> 1) & 3);

    // Load one K-chunk: 4 tiles (Ahi, Alo, Bhi, Blo), 8 cp.async per thread.
    auto load_chunk = [&](int c, uint32_t buf) {
        const size_t kb = (size_t)c * 64;          // byte offset along K
        const char* t0 = (const char*)gAhi + kb;
        const char* t1 = (const char*)gAlo + kb;
        const char* t2 = (const char*)gBhi + kb;
        const char* t3 = (const char*)gBlo + kb;
        const uint32_t so  = lr * ROWB + pc * 16;
        const uint32_t so2 = (lr + 64) * ROWB + pc * 16;
        const size_t go  = (size_t)lr * K * 2 + ls * 16;
        const size_t go2 = (size_t)(lr + 64) * K * 2 + ls * 16;
        cpa16(buf + so,              t0 + go);
        cpa16(buf + so2,             t0 + go2);
        cpa16(buf + BTILE + so,      t1 + go);
        cpa16(buf + BTILE + so2,     t1 + go2);
        cpa16(buf + 2 * BTILE + so,  t2 + go);
        cpa16(buf + 2 * BTILE + so2, t2 + go2);
        cpa16(buf + 3 * BTILE + so,  t3 + go);
        cpa16(buf + 3 * BTILE + so2, t3 + go2);
    };

    load_chunk(0, sb);          cpa_commit();
    load_chunk(1, sb + STAGE);  cpa_commit();

    float acc[4][4][4];
    #pragma unroll
    for (int i = 0; i < 4; i++)
        #pragma unroll
        for (int j = 0; j < 4; j++)
            #pragma unroll
            for (int r = 0; r < 4; r++) acc[i][j][r] = 0.0f;

    // per-lane LDSM addressing (swizzle key invariant under row+16 shifts)
    const int arow = wm * 64 + (lane & 15);
    const int brow = wn * 32 + (lane & 15);
    const uint32_t abase = (uint32_t)(arow * ROWB);
    const uint32_t bbase = (uint32_t)(brow * ROWB);
    const int sa = (arow >> 1) & 3;
    const int sbk = (brow >> 1) & 3;
    const int lc = lane >> 4;                      // logical col16 (0 or 1)
    // physical column byte offsets per ks
    const uint32_t acol0 = (uint32_t)(((lc + 0) ^ sa) * 16);
    const uint32_t acol1 = (uint32_t)(((lc + 2) ^ sa) * 16);
    const uint32_t bcol0 = (uint32_t)(((lc + 0) ^ sbk) * 16);
    const uint32_t bcol1 = (uint32_t)(((lc + 2) ^ sbk) * 16);

    for (int c = 0; c < KC; c++) {
        const uint32_t bp = sb + (uint32_t)(c % 3) * STAGE;
        cpa_wait1();               // chunk c complete (all but newest 1 group)
        __syncthreads();           // publish copies; certify slot (c+2)%3 free

        if (c + 2 < KC) load_chunk(c + 2, sb + (uint32_t)((c + 2) % 3) * STAGE);
        cpa_commit();

        #pragma unroll
        for (int ks = 0; ks < 2; ks++) {
            const uint32_t ac = ks ? acol1 : acol0;
            const uint32_t bc = ks ? bcol1 : bcol0;
            uint32_t ah[4][4], bh[2][4];
            #pragma unroll
            for (int mi = 0; mi < 4; mi++)
                LDSM4(ah[mi], bp + abase + mi * 1024 + ac);
            #pragma unroll
            for (int nb = 0; nb < 2; nb++)
                LDSM4(bh[nb], bp + 2 * BTILE + bbase + nb * 1024 + bc);

            // hi * hi
            #pragma unroll
            for (int mi = 0; mi < 4; mi++)
                #pragma unroll
                for (int nb = 0; nb < 2; nb++) {
                    MMA16816(acc[mi][nb * 2 + 0], ah[mi], bh[nb][0], bh[nb][2]);
                    MMA16816(acc[mi][nb * 2 + 1], ah[mi], bh[nb][1], bh[nb][3]);
                }
            // lo * hi  (reuse bh; al scoped)
            {
                uint32_t al[4][4];
                #pragma unroll
                for (int mi = 0; mi < 4; mi++)
                    LDSM4(al[mi], bp + BTILE + abase + mi * 1024 + ac);
                #pragma unroll
                for (int mi = 0; mi < 4; mi++)
                    #pragma unroll
                    for (int nb = 0; nb < 2; nb++) {
                        MMA16816(acc[mi][nb * 2 + 0], al[mi], bh[nb][0], bh[nb][2]);
                        MMA16816(acc[mi][nb * 2 + 1], al[mi], bh[nb][1], bh[nb][3]);
                    }
            }
            // hi * lo  (reuse ah; bl scoped)
            {
                uint32_t bl[2][4];
                #pragma unroll
                for (int nb = 0; nb < 2; nb++)
                    LDSM4(bl[nb], bp + 3 * BTILE + bbase + nb * 1024 + bc);
                #pragma unroll
                for (int mi = 0; mi < 4; mi++)
                    #pragma unroll
                    for (int nb = 0; nb < 2; nb++) {
                        MMA16816(acc[mi][nb * 2 + 0], ah[mi], bl[nb][0], bl[nb][2]);
                        MMA16816(acc[mi][nb * 2 + 1], ah[mi], bl[nb][1], bl[nb][3]);
                    }
            }
        }
    }

    // Epilogue: fragment layout m16n8: c0,c1 @ (row, 2*(lane%4)); c2,c3 @ row+8
    float* pC = C + (size_t)bz * M * N + (size_t)(m0 + wm * 64) * N + n0 + wn * 32;
    const int er = lane >> 2, ec = (lane & 3) * 2;
    #pragma unroll
    for (int mi = 0; mi < 4; mi++) {
        #pragma unroll
        for (int ni = 0; ni < 4; ni++) {
            float* d0 = pC + (size_t)(mi * 16 + er) * N + ni * 8 + ec;
            float* d1 = d0 + (size_t)8 * N;
            *(float2*)d0 = make_float2(acc[mi][ni][0], acc[mi][ni][1]);
            *(float2*)d1 = make_float2(acc[mi][ni][2], acc[mi][ni][3]);
        }
    }
}

// ---------------------------------------------------------------------------
// fp32 -> (bf16 hi, bf16 lo) elementwise split; 4 elems/thread
// ---------------------------------------------------------------------------
__global__ __launch_bounds__(256)
void split_kernel(const float* __restrict__ x, __nv_bfloat16* __restrict__ hi,
                  __nv_bfloat16* __restrict__ lo) {
    const size_t i = ((size_t)blockIdx.x * 256 + threadIdx.x) * 4;
    const float4 v = *(const float4*)(x + i);
    __nv_bfloat162 h0, h1, l0, l1;
    h0.x = __float2bfloat16(v.x); h0.y = __float2bfloat16(v.y);
    h1.x = __float2bfloat16(v.z); h1.y = __float2bfloat16(v.w);
    l0.x = __float2bfloat16(v.x - __bfloat162float(h0.x));
    l0.y = __float2bfloat16(v.y - __bfloat162float(h0.y));
    l1.x = __float2bfloat16(v.z - __bfloat162float(h1.x));
    l1.y = __float2bfloat16(v.w - __bfloat162float(h1.y));
    ((__nv_bfloat162*)(hi + i))[0] = h0; ((__nv_bfloat162*)(hi + i))[1] = h1;
    ((__nv_bfloat162*)(lo + i))[0] = l0; ((__nv_bfloat162*)(lo + i))[1] = l1;
}

// ---------------------------------------------------------------------------
// K [B, NK, DH] fp32 -> transposed splits [B, DH, NK] bf16 hi/lo
// ---------------------------------------------------------------------------
__global__ __launch_bounds__(256)
void transpose_split_kernel(const float* __restrict__ Kin,
                            __nv_bfloat16* __restrict__ Thi,
                            __nv_bfloat16* __restrict__ Tlo) {
    __shared__ float tile[32][33];
    const int b = blockIdx.z;
    const int n0 = blockIdx.x * 32, d0 = blockIdx.y * 32;
    const int tx = threadIdx.x, ty = threadIdx.y;   // (32, 8)
    const float* src = Kin + (size_t)b * NK * DH;
    #pragma unroll
    for (int j = 0; j < 32; j += 8)
        tile[ty + j][tx] = src[(size_t)(n0 + ty + j) * DH + d0 + tx];
    __syncthreads();
    __nv_bfloat16* th = Thi + (size_t)b * DH * NK;
    __nv_bfloat16* tl = Tlo + (size_t)b * DH * NK;
    #pragma unroll
    for (int j = 0; j < 32; j += 8) {
        const float v = tile[tx][ty + j];
        const __nv_bfloat16 h = __float2bfloat16(v);
        th[(size_t)(d0 + ty + j) * NK + n0 + tx] = h;
        tl[(size_t)(d0 + ty + j) * NK + n0 + tx] = __float2bfloat16(v - __bfloat162float(h));
    }
}

// ---------------------------------------------------------------------------
// Row softmax over NK, emitting split-bf16 probabilities.
// ---------------------------------------------------------------------------
__device__ __forceinline__ void store_split2(__nv_bfloat162* ph, __nv_bfloat162* pl,
                                             float a, float b) {
    __nv_bfloat162 h, l;
    h.x = __float2bfloat16(a); h.y = __float2bfloat16(b);
    l.x = __float2bfloat16(a - __bfloat162float(h.x));
    l.y = __float2bfloat16(b - __bfloat162float(h.y));
    *ph = h; *pl = l;
}

__global__ __launch_bounds__(256)
void softmax_split_kernel(const float* __restrict__ S,
                          __nv_bfloat16* __restrict__ Phi,
                          __nv_bfloat16* __restrict__ Plo) {
    const float* row = S + (size_t)blockIdx.x * NK;
    __nv_bfloat162* ph = (__nv_bfloat162*)(Phi + (size_t)blockIdx.x * NK);
    __nv_bfloat162* pl = (__nv_bfloat162*)(Plo + (size_t)blockIdx.x * NK);
    const int tid = threadIdx.x;

    float4 v0 = *(const float4*)(row + (size_t)tid * 4);
    float4 v1 = *(const float4*)(row + (size_t)(tid + 256) * 4);

    float mx = fmaxf(fmaxf(fmaxf(v0.x, v0.y), fmaxf(v0.z, v0.w)),
                     fmaxf(fmaxf(v1.x, v1.y), fmaxf(v1.z, v1.w)));

    __shared__ float shm[8];
    __shared__ float shs[8];

    #pragma unroll
    for (int o = 16; o; o >>= 1) mx = fmaxf(mx, __shfl_xor_sync(0xffffffffu, mx, o));
    if ((tid & 31) == 0) shm[tid >> 5] = mx;
    __syncthreads();
    mx = shm[0];
    #pragma unroll
    for (int i = 1; i < 8; i++) mx = fmaxf(mx, shm[i]);

    v0.x = __expf(v0.x - mx); v0.y = __expf(v0.y - mx);
    v0.z = __expf(v0.z - mx); v0.w = __expf(v0.w - mx);
    v1.x = __expf(v1.x - mx); v1.y = __expf(v1.y - mx);
    v1.z = __expf(v1.z - mx); v1.w = __expf(v1.w - mx);

    float s = v0.x + v0.y + v0.z + v0.w + v1.x + v1.y + v1.z + v1.w;
    #pragma unroll
    for (int o = 16; o; o >>= 1) s += __shfl_xor_sync(0xffffffffu, s, o);
    if ((tid & 31) == 0) shs[tid >> 5] = s;
    __syncthreads();
    s = 0.0f;
    #pragma unroll
    for (int i = 0; i < 8; i++) s += shs[i];

    const float inv = 1.0f / s;
    v0.x *= inv; v0.y *= inv; v0.z *= inv; v0.w *= inv;
    v1.x *= inv; v1.y *= inv; v1.z *= inv; v1.w *= inv;

    store_split2(ph + (size_t)tid * 2 + 0, pl + (size_t)tid * 2 + 0, v0.x, v0.y);
    store_split2(ph + (size_t)tid * 2 + 1, pl + (size_t)tid * 2 + 1, v0.z, v0.w);
    store_split2(ph + (size_t)(tid + 256) * 2 + 0, pl + (size_t)(tid + 256) * 2 + 0, v1.x, v1.y);
    store_split2(ph + (size_t)(tid + 256) * 2 + 1, pl + (size_t)(tid + 256) * 2 + 1, v1.z, v1.w);
}

// ---------------------------------------------------------------------------
extern "C" void kernel_launch(void* const* d_in, const int* in_sizes, int n_in,
                              void* d_out, int out_size) {
    const float* Q  = (const float*)d_in[0];   // [B, NQ, DH]
    const float* Kp = (const float*)d_in[1];   // [B, NK, DH]
    float* O = (float*)d_out;                  // [B, NQ, DH]

    float* S; __nv_bfloat16 *qhi, *qlo, *khi, *klo, *kthi, *ktlo, *phi, *plo;
    cudaGetSymbolAddress((void**)&S,    g_S);
    cudaGetSymbolAddress((void**)&qhi,  g_Qhi);
    cudaGetSymbolAddress((void**)&qlo,  g_Qlo);
    cudaGetSymbolAddress((void**)&khi,  g_Khi);
    cudaGetSymbolAddress((void**)&klo,  g_Klo);
    cudaGetSymbolAddress((void**)&kthi, g_Kthi);
    cudaGetSymbolAddress((void**)&ktlo, g_Ktlo);
    cudaGetSymbolAddress((void**)&phi,  g_Phi);
    cudaGetSymbolAddress((void**)&plo,  g_Plo);

    cudaFuncSetAttribute(gemm_mma_kernel, cudaFuncAttributeMaxDynamicSharedMemorySize, GEMM_SMEM);

    const int splitBlocks = (BATCH * NQ * DH) / (256 * 4);   // 8192

    split_kernel<<<splitBlocks, 256>>>(Q, qhi, qlo);
    split_kernel<<<splitBlocks, 256>>>(Kp, khi, klo);
    transpose_split_kernel<<<dim3(NK / 32, DH / 32, BATCH), dim3(32, 8)>>>(Kp, kthi, ktlo);

    // S = Q K^T   (M=2048, N=2048, K=512)
    gemm_mma_kernel<<<dim3(NK / 128, NQ / 128, BATCH), 256, GEMM_SMEM>>>(
        qhi, qlo, khi, klo, S, NQ, NK, DH);

    // P = softmax(S), split to bf16 hi/lo
    softmax_split_kernel<<<BATCH * NQ, 256>>>(S, phi, plo);

    // O = P K     (M=2048, N=512, K=2048), B = K^T (transposed splits, K-major)
    gemm_mma_kernel<<<dim3(DH / 128, NQ / 128, BATCH), 256, GEMM_SMEM>>>(
        phi, plo, kthi, ktlo, O, NQ, DH, NK);
}

// round 16
// speedup vs baseline: 1.1748x; 1.0306x over previous
#include <cuda_runtime.h>
#include <cuda_bf16.h>
#include <math.h>
#include <cstdint>

static constexpr int BATCH = 8;
static constexpr int NQ = 2048;
static constexpr int NK = 2048;
static constexpr int DH = 512;

// ---------------- device scratch (no allocs allowed) ----------------
__device__ float g_S[(size_t)BATCH * NQ * NK];                      // 128 MiB
__device__ __nv_bfloat16 g_Qhi[(size_t)BATCH * NQ * DH];
__device__ __nv_bfloat16 g_Qlo[(size_t)BATCH * NQ * DH];
__device__ __nv_bfloat16 g_Khi[(size_t)BATCH * NK * DH];
__device__ __nv_bfloat16 g_Klo[(size_t)BATCH * NK * DH];
__device__ __nv_bfloat16 g_Kthi[(size_t)BATCH * DH * NK];           // K^T [B, DH, NK]
__device__ __nv_bfloat16 g_Ktlo[(size_t)BATCH * DH * NK];
__device__ __nv_bfloat16 g_Phi[(size_t)BATCH * NQ * NK];            // 64 MiB
__device__ __nv_bfloat16 g_Plo[(size_t)BATCH * NQ * NK];

// ---------------- helpers (sm_80-era PTX only: safe on compute_103) --------
__device__ __forceinline__ uint32_t smem_u32(const void* p) {
    uint32_t a;
    asm("{ .reg .u64 t; cvta.to.shared.u64 t, %1; cvt.u32.u64 %0, t; }" : "=r"(a) : "l"(p));
    return a;
}
__device__ __forceinline__ void cpa16(uint32_t dst, const void* src) {
    asm volatile("cp.async.cg.shared.global [%0], [%1], 16;" :: "r"(dst), "l"(src));
}
__device__ __forceinline__ void cpa_commit() { asm volatile("cp.async.commit_group;" ::: "memory"); }
__device__ __forceinline__ void cpa_wait1()  { asm volatile("cp.async.wait_group 1;" ::: "memory"); }

#define LDSM4(r, addr) \
    asm volatile("ldmatrix.sync.aligned.m8n8.x4.shared.b16 {%0,%1,%2,%3}, [%4];" \
                 : "=r"((r)[0]), "=r"((r)[1]), "=r"((r)[2]), "=r"((r)[3]) : "r"(addr))

#define MMA16816(d, a, b0v, b1v) \
    asm volatile("mma.sync.aligned.m16n8k16.row.col.f32.bf16.bf16.f32 " \
                 "{%0,%1,%2,%3}, {%4,%5,%6,%7}, {%8,%9}, {%0,%1,%2,%3};" \
                 : "+f"((d)[0]), "+f"((d)[1]), "+f"((d)[2]), "+f"((d)[3]) \
                 : "r"((a)[0]), "r"((a)[1]), "r"((a)[2]), "r"((a)[3]), \
                   "r"(b0v), "r"(b1v))

// ---------------------------------------------------------------------------
// Split-bf16 GEMM via mma.sync: C = (Ahi+Alo)*(Bhi+Blo)^T, dropping lo*lo.
// 128x128 tile/CTA, 256 threads, 2x4 warp grid -> 64x32 warp tiles, BK=32.
// SMEM: 64B rows with XOR swizzle (phys_col16 = col16 ^ ((row>>1)&3)) ->
// conflict-free LDSM with NO padding. 3-stage ring, ONE __syncthreads per
// chunk. Per ks-step: ALL 12 LDSM issued up front, refill cp.async issued
// between LDSM and MMA, then one uninterrupted 48-MMA burst.
// ---------------------------------------------------------------------------
static constexpr int ROWB = 64;                   // bytes per smem row (no pad)
static constexpr int BTILE = 128 * ROWB;          // 8192 B per operand tile
static constexpr int STAGE = 4 * BTILE;           // Ahi|Alo|Bhi|Blo (32768 B)
static constexpr int STAGES = 3;
static constexpr int GEMM_SMEM = STAGES * STAGE;  // 98304 B

__global__ __launch_bounds__(256, 2)
void gemm_mma_kernel(const __nv_bfloat16* __restrict__ Ahi, const __nv_bfloat16* __restrict__ Alo,
                     const __nv_bfloat16* __restrict__ Bhi, const __nv_bfloat16* __restrict__ Blo,
                     float* __restrict__ C, int M, int N, int K)
{
    extern __shared__ char smem[];
    const uint32_t sb = smem_u32(smem);
    const int tid = threadIdx.x;
    const int warp = tid >> 5, lane = tid & 31;
    const int wm = warp >> 2, wn = warp & 3;       // 2 x 4 warp grid
    const int bz = blockIdx.z;
    const int m0 = blockIdx.y * 128, n0 = blockIdx.x * 128;

    const size_t offA = (size_t)bz * M * K + (size_t)m0 * K;
    const size_t offB = (size_t)bz * N * K + (size_t)n0 * K;
    const __nv_bfloat16* gAhi = Ahi + offA;
    const __nv_bfloat16* gAlo = Alo + offA;
    const __nv_bfloat16* gBhi = Bhi + offB;
    const __nv_bfloat16* gBlo = Blo + offB;

    const int KC = K / 32;         // K-chunks

    const int lr = tid >> 2;       // 0..63  (load row)
    const int ls = tid & 3;        // 0..3   (logical 16B chunk within 64B row)
    // swizzled physical column for this thread's rows (invariant for lr and lr+64)
    const int pc = ls ^ ((lr >> 1) & 3);

    // Load one K-chunk: 4 tiles (Ahi, Alo, Bhi, Blo), 8 cp.async per thread.
    auto load_chunk = [&](int c, uint32_t buf) {
        const size_t kb = (size_t)c * 64;          // byte offset along K
        const char* t0 = (const char*)gAhi + kb;
        const char* t1 = (const char*)gAlo + kb;
        const char* t2 = (const char*)gBhi + kb;
        const char* t3 = (const char*)gBlo + kb;
        const uint32_t so  = lr * ROWB + pc * 16;
        const uint32_t so2 = (lr + 64) * ROWB + pc * 16;
        const size_t go  = (size_t)lr * K * 2 + ls * 16;
        const size_t go2 = (size_t)(lr + 64) * K * 2 + ls * 16;
        cpa16(buf + so,              t0 + go);
        cpa16(buf + so2,             t0 + go2);
        cpa16(buf + BTILE + so,      t1 + go);
        cpa16(buf + BTILE + so2,     t1 + go2);
        cpa16(buf + 2 * BTILE + so,  t2 + go);
        cpa16(buf + 2 * BTILE + so2, t2 + go2);
        cpa16(buf + 3 * BTILE + so,  t3 + go);
        cpa16(buf + 3 * BTILE + so2, t3 + go2);
    };

    load_chunk(0, sb);          cpa_commit();
    load_chunk(1, sb + STAGE);  cpa_commit();

    float acc[4][4][4];
    #pragma unroll
    for (int i = 0; i < 4; i++)
        #pragma unroll
        for (int j = 0; j < 4; j++)
            #pragma unroll
            for (int r = 0; r < 4; r++) acc[i][j][r] = 0.0f;

    // per-lane LDSM addressing (swizzle key invariant under row+16 shifts)
    const int arow = wm * 64 + (lane & 15);
    const int brow = wn * 32 + (lane & 15);
    const uint32_t abase = (uint32_t)(arow * ROWB);
    const uint32_t bbase = (uint32_t)(brow * ROWB);
    const int sa = (arow >> 1) & 3;
    const int sbk = (brow >> 1) & 3;
    const int lc = lane >> 4;                      // logical col16 (0 or 1)
    // physical column byte offsets per ks
    const uint32_t acol0 = (uint32_t)(((lc + 0) ^ sa) * 16);
    const uint32_t acol1 = (uint32_t)(((lc + 2) ^ sa) * 16);
    const uint32_t bcol0 = (uint32_t)(((lc + 0) ^ sbk) * 16);
    const uint32_t bcol1 = (uint32_t)(((lc + 2) ^ sbk) * 16);

    for (int c = 0; c < KC; c++) {
        const uint32_t bp = sb + (uint32_t)(c % 3) * STAGE;
        cpa_wait1();               // chunk c complete (all but newest 1 group)
        __syncthreads();           // publish copies; certify slot (c+2)%3 free

        #pragma unroll
        for (int ks = 0; ks < 2; ks++) {
            const uint32_t ac = ks ? acol1 : acol0;
            const uint32_t bc = ks ? bcol1 : bcol0;

            // ---- all 12 LDSM up front (hi first, then lo) ----
            uint32_t ah[4][4], bh[2][4], al[4][4], bl[2][4];
            #pragma unroll
            for (int mi = 0; mi < 4; mi++)
                LDSM4(ah[mi], bp + abase + mi * 1024 + ac);
            #pragma unroll
            for (int nb = 0; nb < 2; nb++)
                LDSM4(bh[nb], bp + 2 * BTILE + bbase + nb * 1024 + bc);
            #pragma unroll
            for (int mi = 0; mi < 4; mi++)
                LDSM4(al[mi], bp + BTILE + abase + mi * 1024 + ac);
            #pragma unroll
            for (int nb = 0; nb < 2; nb++)
                LDSM4(bl[nb], bp + 3 * BTILE + bbase + nb * 1024 + bc);

            // refill issues while LDSM results are in flight (ks==0 only)
            if (ks == 0) {
                if (c + 2 < KC) load_chunk(c + 2, sb + (uint32_t)((c + 2) % 3) * STAGE);
                cpa_commit();
            }

            // ---- one uninterrupted 48-MMA burst: hh, lh, hl ----
            #pragma unroll
            for (int mi = 0; mi < 4; mi++)
                #pragma unroll
                for (int nb = 0; nb < 2; nb++) {
                    MMA16816(acc[mi][nb * 2 + 0], ah[mi], bh[nb][0], bh[nb][2]);
                    MMA16816(acc[mi][nb * 2 + 1], ah[mi], bh[nb][1], bh[nb][3]);
                }
            #pragma unroll
            for (int mi = 0; mi < 4; mi++)
                #pragma unroll
                for (int nb = 0; nb < 2; nb++) {
                    MMA16816(acc[mi][nb * 2 + 0], al[mi], bh[nb][0], bh[nb][2]);
                    MMA16816(acc[mi][nb * 2 + 1], al[mi], bh[nb][1], bh[nb][3]);
                }
            #pragma unroll
            for (int mi = 0; mi < 4; mi++)
                #pragma unroll
                for (int nb = 0; nb < 2; nb++) {
                    MMA16816(acc[mi][nb * 2 + 0], ah[mi], bl[nb][0], bl[nb][2]);
                    MMA16816(acc[mi][nb * 2 + 1], ah[mi], bl[nb][1], bl[nb][3]);
                }
        }
    }

    // Epilogue: fragment layout m16n8: c0,c1 @ (row, 2*(lane%4)); c2,c3 @ row+8
    float* pC = C + (size_t)bz * M * N + (size_t)(m0 + wm * 64) * N + n0 + wn * 32;
    const int er = lane >> 2, ec = (lane & 3) * 2;
    #pragma unroll
    for (int mi = 0; mi < 4; mi++) {
        #pragma unroll
        for (int ni = 0; ni < 4; ni++) {
            float* d0 = pC + (size_t)(mi * 16 + er) * N + ni * 8 + ec;
            float* d1 = d0 + (size_t)8 * N;
            *(float2*)d0 = make_float2(acc[mi][ni][0], acc[mi][ni][1]);
            *(float2*)d1 = make_float2(acc[mi][ni][2], acc[mi][ni][3]);
        }
    }
}

// ---------------------------------------------------------------------------
// fp32 -> (bf16 hi, bf16 lo) elementwise split; 4 elems/thread
// ---------------------------------------------------------------------------
__global__ __launch_bounds__(256)
void split_kernel(const float* __restrict__ x, __nv_bfloat16* __restrict__ hi,
                  __nv_bfloat16* __restrict__ lo) {
    const size_t i = ((size_t)blockIdx.x * 256 + threadIdx.x) * 4;
    const float4 v = *(const float4*)(x + i);
    __nv_bfloat162 h0, h1, l0, l1;
    h0.x = __float2bfloat16(v.x); h0.y = __float2bfloat16(v.y);
    h1.x = __float2bfloat16(v.z); h1.y = __float2bfloat16(v.w);
    l0.x = __float2bfloat16(v.x - __bfloat162float(h0.x));
    l0.y = __float2bfloat16(v.y - __bfloat162float(h0.y));
    l1.x = __float2bfloat16(v.z - __bfloat162float(h1.x));
    l1.y = __float2bfloat16(v.w - __bfloat162float(h1.y));
    ((__nv_bfloat162*)(hi + i))[0] = h0; ((__nv_bfloat162*)(hi + i))[1] = h1;
    ((__nv_bfloat162*)(lo + i))[0] = l0; ((__nv_bfloat162*)(lo + i))[1] = l1;
}

// ---------------------------------------------------------------------------
// K [B, NK, DH] fp32 -> transposed splits [B, DH, NK] bf16 hi/lo
// ---------------------------------------------------------------------------
__global__ __launch_bounds__(256)
void transpose_split_kernel(const float* __restrict__ Kin,
                            __nv_bfloat16* __restrict__ Thi,
                            __nv_bfloat16* __restrict__ Tlo) {
    __shared__ float tile[32][33];
    const int b = blockIdx.z;
    const int n0 = blockIdx.x * 32, d0 = blockIdx.y * 32;
    const int tx = threadIdx.x, ty = threadIdx.y;   // (32, 8)
    const float* src = Kin + (size_t)b * NK * DH;
    #pragma unroll
    for (int j = 0; j < 32; j += 8)
        tile[ty + j][tx] = src[(size_t)(n0 + ty + j) * DH + d0 + tx];
    __syncthreads();
    __nv_bfloat16* th = Thi + (size_t)b * DH * NK;
    __nv_bfloat16* tl = Tlo + (size_t)b * DH * NK;
    #pragma unroll
    for (int j = 0; j < 32; j += 8) {
        const float v = tile[tx][ty + j];
        const __nv_bfloat16 h = __float2bfloat16(v);
        th[(size_t)(d0 + ty + j) * NK + n0 + tx] = h;
        tl[(size_t)(d0 + ty + j) * NK + n0 + tx] = __float2bfloat16(v - __bfloat162float(h));
    }
}

// ---------------------------------------------------------------------------
// Row softmax over NK, emitting split-bf16 probabilities.
// ---------------------------------------------------------------------------
__device__ __forceinline__ void store_split2(__nv_bfloat162* ph, __nv_bfloat162* pl,
                                             float a, float b) {
    __nv_bfloat162 h, l;
    h.x = __float2bfloat16(a); h.y = __float2bfloat16(b);
    l.x = __float2bfloat16(a - __bfloat162float(h.x));
    l.y = __float2bfloat16(b - __bfloat162float(h.y));
    *ph = h; *pl = l;
}

__global__ __launch_bounds__(256)
void softmax_split_kernel(const float* __restrict__ S,
                          __nv_bfloat16* __restrict__ Phi,
                          __nv_bfloat16* __restrict__ Plo) {
    const float* row = S + (size_t)blockIdx.x * NK;
    __nv_bfloat162* ph = (__nv_bfloat162*)(Phi + (size_t)blockIdx.x * NK);
    __nv_bfloat162* pl = (__nv_bfloat162*)(Plo + (size_t)blockIdx.x * NK);
    const int tid = threadIdx.x;

    float4 v0 = *(const float4*)(row + (size_t)tid * 4);
    float4 v1 = *(const float4*)(row + (size_t)(tid + 256) * 4);

    float mx = fmaxf(fmaxf(fmaxf(v0.x, v0.y), fmaxf(v0.z, v0.w)),
                     fmaxf(fmaxf(v1.x, v1.y), fmaxf(v1.z, v1.w)));

    __shared__ float shm[8];
    __shared__ float shs[8];

    #pragma unroll
    for (int o = 16; o; o >>= 1) mx = fmaxf(mx, __shfl_xor_sync(0xffffffffu, mx, o));
    if ((tid & 31) == 0) shm[tid >> 5] = mx;
    __syncthreads();
    mx = shm[0];
    #pragma unroll
    for (int i = 1; i < 8; i++) mx = fmaxf(mx, shm[i]);

    v0.x = __expf(v0.x - mx); v0.y = __expf(v0.y - mx);
    v0.z = __expf(v0.z - mx); v0.w = __expf(v0.w - mx);
    v1.x = __expf(v1.x - mx); v1.y = __expf(v1.y - mx);
    v1.z = __expf(v1.z - mx); v1.w = __expf(v1.w - mx);

    float s = v0.x + v0.y + v0.z + v0.w + v1.x + v1.y + v1.z + v1.w;
    #pragma unroll
    for (int o = 16; o; o >>= 1) s += __shfl_xor_sync(0xffffffffu, s, o);
    if ((tid & 31) == 0) shs[tid >> 5] = s;
    __syncthreads();
    s = 0.0f;
    #pragma unroll
    for (int i = 0; i < 8; i++) s += shs[i];

    const float inv = 1.0f / s;
    v0.x *= inv; v0.y *= inv; v0.z *= inv; v0.w *= inv;
    v1.x *= inv; v1.y *= inv; v1.z *= inv; v1.w *= inv;

    store_split2(ph + (size_t)tid * 2 + 0, pl + (size_t)tid * 2 + 0, v0.x, v0.y);
    store_split2(ph + (size_t)tid * 2 + 1, pl + (size_t)tid * 2 + 1, v0.z, v0.w);
    store_split2(ph + (size_t)(tid + 256) * 2 + 0, pl + (size_t)(tid + 256) * 2 + 0, v1.x, v1.y);
    store_split2(ph + (size_t)(tid + 256) * 2 + 1, pl + (size_t)(tid + 256) * 2 + 1, v1.z, v1.w);
}

// ---------------------------------------------------------------------------
extern "C" void kernel_launch(void* const* d_in, const int* in_sizes, int n_in,
                              void* d_out, int out_size) {
    const float* Q  = (const float*)d_in[0];   // [B, NQ, DH]
    const float* Kp = (const float*)d_in[1];   // [B, NK, DH]
    float* O = (float*)d_out;                  // [B, NQ, DH]

    float* S; __nv_bfloat16 *qhi, *qlo, *khi, *klo, *kthi, *ktlo, *phi, *plo;
    cudaGetSymbolAddress((void**)&S,    g_S);
    cudaGetSymbolAddress((void**)&qhi,  g_Qhi);
    cudaGetSymbolAddress((void**)&qlo,  g_Qlo);
    cudaGetSymbolAddress((void**)&khi,  g_Khi);
    cudaGetSymbolAddress((void**)&klo,  g_Klo);
    cudaGetSymbolAddress((void**)&kthi, g_Kthi);
    cudaGetSymbolAddress((void**)&ktlo, g_Ktlo);
    cudaGetSymbolAddress((void**)&phi,  g_Phi);
    cudaGetSymbolAddress((void**)&plo,  g_Plo);

    cudaFuncSetAttribute(gemm_mma_kernel, cudaFuncAttributeMaxDynamicSharedMemorySize, GEMM_SMEM);

    const int splitBlocks = (BATCH * NQ * DH) / (256 * 4);   // 8192

    split_kernel<<<splitBlocks, 256>>>(Q, qhi, qlo);
    split_kernel<<<splitBlocks, 256>>>(Kp, khi, klo);
    transpose_split_kernel<<<dim3(NK / 32, DH / 32, BATCH), dim3(32, 8)>>>(Kp, kthi, ktlo);

    // S = Q K^T   (M=2048, N=2048, K=512)
    gemm_mma_kernel<<<dim3(NK / 128, NQ / 128, BATCH), 256, GEMM_SMEM>>>(
        qhi, qlo, khi, klo, S, NQ, NK, DH);

    // P = softmax(S), split to bf16 hi/lo
    softmax_split_kernel<<<BATCH * NQ, 256>>>(S, phi, plo);

    // O = P K     (M=2048, N=512, K=2048), B = K^T (transposed splits, K-major)
    gemm_mma_kernel<<<dim3(DH / 128, NQ / 128, BATCH), 256, GEMM_SMEM>>>(
        phi, plo, kthi, ktlo, O, NQ, DH, NK);
}